// round 7
// baseline (speedup 1.0000x reference)
#include <cuda_runtime.h>
#include <cuda_bf16.h>
#include <cstdint>

// Problem constants
#define B_   4
#define S_   2048
#define D_   1024
#define NC_  16
#define NK_  32768
#define R_   128
#define TK_  8
#define NTOK (B_*S_)          // 8192 tokens
#define NSPLIT4 4
#define NSPL4 (NK_/NSPLIT4)   // 8192 knowledge rows per split
#define CHN  64               // knowledge rows per chunk
#define NCH  (NSPL4/CHN)      // 128 chunks
#define NCAND 8               // top-8 per split -> 32 candidates/token

#define SCALE_ 0.08838834764831845f

#define QSTR 136              // bf16 smem row stride (Q/K tiles)
#define SROWB 144             // score tile row stride in BYTES (72 bf16)

// smem offsets (bytes)
#define QS_OFF 0
#define KS_OFF (128*QSTR*2)              // 34816
#define KSZ    (64*QSTR*2)               // 17408 per K buffer
#define SS_OFF (KS_OFF + 2*KSZ)          // 69632
#define SSZ    (128*SROWB)               // 18432 per bf16 score buffer
#define SMEM_SC (SS_OFF + 2*SSZ)         // 106496

// ---------------- scratch ----------------
__device__ float          g_SC [B_*D_*R_];
__device__ float          g_Q  [NTOK*R_];
__device__ __nv_bfloat16  g_Qbf[NTOK*R_];
__device__ __nv_bfloat16  g_Kbf[NK_*R_];
__device__ int            g_ci [NTOK*NSPLIT4*NCAND];
__device__ float          g_w  [NTOK*TK_];
__device__ int            g_i  [NTOK*TK_];

// ---------------- PTX helpers ----------------
__device__ __forceinline__ uint32_t smem_u32(const void* p) {
    uint32_t a;
    asm("{ .reg .u64 t; cvta.to.shared.u64 t, %1; cvt.u32.u64 %0, t; }" : "=r"(a) : "l"(p));
    return a;
}
__device__ __forceinline__ void ldsm_x4(uint32_t& r0, uint32_t& r1, uint32_t& r2, uint32_t& r3,
                                        uint32_t addr) {
    asm volatile("ldmatrix.sync.aligned.m8n8.x4.shared.b16 {%0,%1,%2,%3}, [%4];"
                 : "=r"(r0), "=r"(r1), "=r"(r2), "=r"(r3) : "r"(addr));
}
__device__ __forceinline__ void cp_async16(uint32_t saddr, const void* gptr) {
    asm volatile("cp.async.cg.shared.global [%0], [%1], 16;" :: "r"(saddr), "l"(gptr));
}
__device__ __forceinline__ void cp_commit() { asm volatile("cp.async.commit_group;"); }
__device__ __forceinline__ void cp_wait0()  { asm volatile("cp.async.wait_group 0;" ::: "memory"); }

__device__ __forceinline__ void mma_bf16(float c[4], uint32_t a0, uint32_t a1, uint32_t a2,
                                         uint32_t a3, uint32_t b0, uint32_t b1) {
    asm volatile(
        "mma.sync.aligned.m16n8k16.row.col.f32.bf16.bf16.f32 "
        "{%0,%1,%2,%3}, {%4,%5,%6,%7}, {%8,%9}, {%0,%1,%2,%3};"
        : "+f"(c[0]), "+f"(c[1]), "+f"(c[2]), "+f"(c[3])
        : "r"(a0), "r"(a1), "r"(a2), "r"(a3), "r"(b0), "r"(b1));
}
__device__ __forceinline__ uint32_t bf16pack(float lo, float hi) {
    uint32_t r;
    asm("cvt.rn.bf16x2.f32 %0, %1, %2;" : "=r"(r) : "f"(hi), "f"(lo));
    return r;
}

// ---------------- K1: shared_compress ----------------
__global__ void sc_kernel(const float* __restrict__ mw, const float* __restrict__ cn) {
    int b = blockIdx.x, d = blockIdx.y, r = threadIdx.x;
    float acc = 0.f;
#pragma unroll
    for (int n = 0; n < NC_; n++)
        acc = fmaf(mw[b*NC_ + n], cn[((size_t)n*D_ + d)*R_ + r], acc);
    g_SC[((size_t)b*D_ + d)*R_ + r] = acc;
}

// ---------------- K1b: convert K -> bf16 ----------------
__global__ void kbf_kernel(const float4* __restrict__ kK) {
    int i = blockIdx.x*blockDim.x + threadIdx.x;
    float4 v = kK[i];
    __nv_bfloat16* d = g_Kbf + (size_t)i*4;
    d[0] = __float2bfloat16(v.x); d[1] = __float2bfloat16(v.y);
    d[2] = __float2bfloat16(v.z); d[3] = __float2bfloat16(v.w);
}

// ---------------- K2: Q projection (fp32 exact, d-ascending chain) ----------------
__global__ void q_kernel(const float* __restrict__ x) {
    __shared__ float xs[32][68];
    __shared__ float scs[32][128];
    int tid = threadIdx.x;
    int b = blockIdx.y, s0 = blockIdx.x*64;

    float acc[4][8];
#pragma unroll
    for (int i = 0; i < 4; i++)
#pragma unroll
        for (int j = 0; j < 8; j++) acc[i][j] = 0.f;

    int tx = (tid & 15)*8;
    int ty = (tid >> 4)*4;

    for (int d0 = 0; d0 < D_; d0 += 32) {
#pragma unroll
        for (int i = 0; i < 2; i++) {
            int idx = tid + 256*i;
            int s = idx >> 3, g = idx & 7;
            float4 v = *(const float4*)(x + (((size_t)b*S_) + s0 + s)*D_ + d0 + 4*g);
            xs[4*g+0][s] = v.x; xs[4*g+1][s] = v.y; xs[4*g+2][s] = v.z; xs[4*g+3][s] = v.w;
        }
#pragma unroll
        for (int i = 0; i < 4; i++) {
            int idx = tid + 256*i;
            int dd = idx >> 5, g = idx & 31;
            *(float4*)&scs[dd][4*g] = *(const float4*)(g_SC + (((size_t)b*D_) + d0 + dd)*R_ + 4*g);
        }
        __syncthreads();
#pragma unroll
        for (int dd = 0; dd < 32; dd++) {
            float q[4] = {xs[dd][ty], xs[dd][ty+1], xs[dd][ty+2], xs[dd][ty+3]};
            float4 ka = *(float4*)&scs[dd][tx];
            float4 kb = *(float4*)&scs[dd][tx+4];
            float k[8] = {ka.x,ka.y,ka.z,ka.w, kb.x,kb.y,kb.z,kb.w};
#pragma unroll
            for (int i = 0; i < 4; i++)
#pragma unroll
                for (int j = 0; j < 8; j++) acc[i][j] = fmaf(q[i], k[j], acc[i][j]);
        }
        __syncthreads();
    }
#pragma unroll
    for (int i = 0; i < 4; i++) {
        int tok = b*S_ + s0 + ty + i;
#pragma unroll
        for (int j = 0; j < 8; j++) {
            g_Q  [(size_t)tok*R_ + tx + j] = acc[i][j];
            g_Qbf[(size_t)tok*R_ + tx + j] = __float2bfloat16(acc[i][j]);
        }
    }
}

// ---------------- K3: bf16 mma.sync scores + per-split top-8, scan overlapped ----------------
__global__ void __launch_bounds__(256, 2) score_mma_kernel() {
    extern __shared__ char sm[];
    __nv_bfloat16 (*Qs)[QSTR] = (__nv_bfloat16(*)[QSTR])(sm + QS_OFF);

    int tid  = threadIdx.x;
    int wid  = tid >> 5;
    int lane = tid & 31;
    int t8   = lane & 7;
    int tl   = lane >> 3;

    int wm = wid & 1;            // m half (64 tokens)
    int wn = wid >> 1;           // n quarter (16 knowledge)

    int token0 = blockIdx.x * 128;
    int split  = blockIdx.y;
    int nbase0 = split * NSPL4;

    uint32_t smbase = smem_u32(sm);
    uint32_t qs_u32 = smbase + QS_OFF;
    uint32_t ks_u32 = smbase + KS_OFF;

    // per-thread ldmatrix address offsets (bytes)
    uint32_t aoff[4];
#pragma unroll
    for (int mf = 0; mf < 4; mf++)
        aoff[mf] = (uint32_t)((wm*64 + mf*16 + (tl & 1)*8 + t8)*QSTR + (tl >> 1)*8) * 2;
    uint32_t boff = (uint32_t)((wn*16 + (tl >> 1)*8 + t8)*QSTR + (tl & 1)*8) * 2;

    // ---- preload Q tile (128 tokens x 128 bf16)
    {
        const uint4* src = (const uint4*)(g_Qbf + (size_t)token0 * R_);
#pragma unroll
        for (int i = 0; i < 8; i++) {
            int idx = tid + 256*i;
            int row = idx >> 4, c = idx & 15;
            *(uint4*)&Qs[row][c*8] = src[idx];
        }
    }
    // ---- preload first K chunk via cp.async
    {
        const uint4* src = (const uint4*)(g_Kbf + (size_t)nbase0 * R_);
#pragma unroll
        for (int i = 0; i < 4; i++) {
            int idx = tid + 256*i;
            int row = idx >> 4, c = idx & 15;
            cp_async16(ks_u32 + (uint32_t)(row*QSTR + c*8)*2, src + idx);
        }
        cp_commit();
    }

    int tok  = tid & 127;
    int half = tid >> 7;

    // per-thread top-8 over its half of the n-range of its token
    float ts[NCAND]; int ti[NCAND];
#pragma unroll
    for (int k = 0; k < NCAND; k++) { ts[k] = -3.402823466e38f; ti[k] = 0; }

    // scan base within a score buffer (bytes)
    uint32_t scanOff = (uint32_t)tok*SROWB + (uint32_t)half*64;

    for (int ch = 0; ch < NCH; ch++) {
        int p = ch & 1;
        cp_wait0();
        __syncthreads();   // K[p] arrived; Ss[p] scans (from chunk ch-1) done

        // ---- prefetch next K chunk into K[p^1]
        if (ch + 1 < NCH) {
            const uint4* src = (const uint4*)(g_Kbf + (size_t)(nbase0 + (ch+1)*CHN) * R_);
            uint32_t dst = ks_u32 + (uint32_t)(p ^ 1)*KSZ;
#pragma unroll
            for (int i = 0; i < 4; i++) {
                int idx = tid + 256*i;
                int row = idx >> 4, c = idx & 15;
                cp_async16(dst + (uint32_t)(row*QSTR + c*8)*2, src + idx);
            }
        }
        cp_commit();

        // ---- MMA over K[p], with scan of Ss[p^1] (chunk ch-1) interleaved
        float c[4][2][4];
#pragma unroll
        for (int mf = 0; mf < 4; mf++)
#pragma unroll
            for (int nf = 0; nf < 2; nf++)
#pragma unroll
                for (int e = 0; e < 4; e++) c[mf][nf][e] = 0.f;

        uint32_t kbuf = ks_u32 + (uint32_t)p*KSZ;
        const char* scanBase = sm + SS_OFF + (p^1)*SSZ + scanOff;
        int nbPrev = nbase0 + (ch-1)*CHN + half*32;
        bool doScan = (ch > 0);

#pragma unroll
        for (int ks = 0; ks < 8; ks++) {
            uint32_t kb = (uint32_t)(ks*16)*2;
            uint32_t b0, b1, b2, b3;
            ldsm_x4(b0, b1, b2, b3, kbuf + boff + kb);
            uint32_t a[4][4];
#pragma unroll
            for (int mf = 0; mf < 4; mf++)
                ldsm_x4(a[mf][0], a[mf][1], a[mf][2], a[mf][3], qs_u32 + aoff[mf] + kb);
#pragma unroll
            for (int mf = 0; mf < 4; mf++) {
                mma_bf16(c[mf][0], a[mf][0], a[mf][1], a[mf][2], a[mf][3], b0, b1);
                mma_bf16(c[mf][1], a[mf][0], a[mf][1], a[mf][2], a[mf][3], b2, b3);
            }
            // scan piece (8 packed bf16 scores) on odd k-steps
            if ((ks & 1) && doScan) {
                int piece = ks >> 1;             // 0..3
                uint4 v = *(const uint4*)(scanBase + piece*16);
                uint32_t wreg[4] = {v.x, v.y, v.z, v.w};
#pragma unroll
                for (int j = 0; j < 4; j++) {
#pragma unroll
                    for (int hl = 0; hl < 2; hl++) {
                        float s = __uint_as_float(hl ? (wreg[j] & 0xFFFF0000u)
                                                     : (wreg[j] << 16));
                        if (s > ts[NCAND-1]) {
                            int ni = nbPrev + piece*8 + j*2 + hl;
#pragma unroll
                            for (int k = 0; k < NCAND; k++) {
                                if (s > ts[k]) {
                                    float tv = ts[k]; ts[k] = s; s = tv;
                                    int tn = ti[k]; ti[k] = ni; ni = tn;
                                }
                            }
                        }
                    }
                }
            }
        }

        // ---- dump C fragments (packed bf16) into Ss[p]
        {
            int g = lane >> 2, tig = lane & 3;
            char* sb = sm + SS_OFF + p*SSZ;
#pragma unroll
            for (int mf = 0; mf < 4; mf++) {
#pragma unroll
                for (int nf = 0; nf < 2; nf++) {
                    int row = wm*64 + mf*16 + g;
                    int col = wn*16 + nf*8 + tig*2;
                    *(uint32_t*)(sb + row*SROWB + col*2)       = bf16pack(c[mf][nf][0], c[mf][nf][1]);
                    *(uint32_t*)(sb + (row+8)*SROWB + col*2)   = bf16pack(c[mf][nf][2], c[mf][nf][3]);
                }
            }
        }
    }

    // ---- scan the final chunk
    __syncthreads();
    {
        int pl = (NCH-1) & 1;                       // = 1
        const char* scanBase = sm + SS_OFF + pl*SSZ + scanOff;
        int nb = nbase0 + (NCH-1)*CHN + half*32;
#pragma unroll
        for (int piece = 0; piece < 4; piece++) {
            uint4 v = *(const uint4*)(scanBase + piece*16);
            uint32_t wreg[4] = {v.x, v.y, v.z, v.w};
#pragma unroll
            for (int j = 0; j < 4; j++) {
#pragma unroll
                for (int hl = 0; hl < 2; hl++) {
                    float s = __uint_as_float(hl ? (wreg[j] & 0xFFFF0000u)
                                                 : (wreg[j] << 16));
                    if (s > ts[NCAND-1]) {
                        int ni = nb + piece*8 + j*2 + hl;
#pragma unroll
                        for (int k = 0; k < NCAND; k++) {
                            if (s > ts[k]) {
                                float tv = ts[k]; ts[k] = s; s = tv;
                                int tn = ti[k]; ti[k] = ni; ni = tn;
                            }
                        }
                    }
                }
            }
        }
    }

    // ---- merge the two halves' top-8 lists (stage in free buffer 0)
    __syncthreads();
    float* stageS = (float*)(sm + SS_OFF);
    int*   stageI = (int*)(sm + SS_OFF) + 128*NCAND;
    if (tid >= 128) {
#pragma unroll
        for (int k = 0; k < NCAND; k++) {
            stageS[tok*NCAND + k] = ts[k];
            stageI[tok*NCAND + k] = ti[k];
        }
    }
    __syncthreads();
    if (tid < 128) {
#pragma unroll
        for (int k2 = 0; k2 < NCAND; k2++) {
            float s = stageS[tok*NCAND + k2];
            int  ni = stageI[tok*NCAND + k2];
            if (s > ts[NCAND-1]) {
#pragma unroll
                for (int k = 0; k < NCAND; k++) {
                    if (s > ts[k]) {
                        float tv = ts[k]; ts[k] = s; s = tv;
                        int tn = ti[k]; ti[k] = ni; ni = tn;
                    }
                }
            }
        }
        int gtok = token0 + tok;
#pragma unroll
        for (int k = 0; k < NCAND; k++)
            g_ci[((size_t)gtok*NSPLIT4 + split)*NCAND + k] = ti[k];
    }
}

// ---------------- K4: exact fp32 rescore of 32 candidates + softmax ----------------
__global__ void rescore_kernel(const float* __restrict__ kK, float* __restrict__ out, int out_size) {
    __shared__ float qs[8][128];
    int wid = threadIdx.x >> 5;
    int lane = threadIdx.x & 31;
    int t = blockIdx.x*8 + wid;

    {
        float4 v = *(const float4*)(g_Q + (size_t)t*R_ + 4*lane);
        *(float4*)&qs[wid][4*lane] = v;
    }
    __syncwarp();

    int cand = g_ci[(size_t)t*32 + lane];
    const float4* kr = (const float4*)(kK + (size_t)cand*R_);
    float acc = 0.f;
#pragma unroll
    for (int r4 = 0; r4 < 32; r4++) {
        float4 k4 = kr[r4];
        const float* q4 = &qs[wid][4*r4];
        acc = fmaf(q4[0], k4.x, acc);
        acc = fmaf(q4[1], k4.y, acc);
        acc = fmaf(q4[2], k4.z, acc);
        acc = fmaf(q4[3], k4.w, acc);
    }
    float v = acc; int id = cand;
    float selv[TK_]; int seli[TK_];
#pragma unroll
    for (int k = 0; k < TK_; k++) {
        float bv = v; int bi = id;
#pragma unroll
        for (int off = 16; off > 0; off >>= 1) {
            float ov = __shfl_xor_sync(0xffffffffu, bv, off);
            int   oi = __shfl_xor_sync(0xffffffffu, bi, off);
            if (ov > bv || (ov == bv && oi < bi)) { bv = ov; bi = oi; }
        }
        selv[k] = bv; seli[k] = bi;
        if (id == bi) v = -3.402823466e38f;
    }
    float sv0 = selv[0] * SCALE_;
    float e[TK_]; float sum = 0.f;
#pragma unroll
    for (int k = 0; k < TK_; k++) { e[k] = expf(selv[k]*SCALE_ - sv0); sum += e[k]; }

    const int NBSD = B_*S_*D_;
    bool extended = (out_size >= NBSD + 2*NTOK*TK_);
    if (lane < TK_) {
        float w = e[lane] / sum;
        g_w[(size_t)t*TK_ + lane] = w;
        g_i[(size_t)t*TK_ + lane] = seli[lane];
        if (extended) {
            out[NBSD + (size_t)t*TK_ + lane]            = (float)seli[lane];
            out[NBSD + NTOK*TK_ + (size_t)t*TK_ + lane] = w;
        }
    }
}

// ---------------- K5: gather + weighted sum over V ----------------
__global__ void gather_kernel(const float4* __restrict__ V4, float4* __restrict__ out4) {
    int t = blockIdx.x;
    __shared__ float ws[TK_];
    __shared__ int   is[TK_];
    if (threadIdx.x < TK_) {
        ws[threadIdx.x] = g_w[(size_t)t*TK_ + threadIdx.x];
        is[threadIdx.x] = g_i[(size_t)t*TK_ + threadIdx.x];
    }
    __syncthreads();
    int d4 = threadIdx.x;
    float4 acc = make_float4(0.f, 0.f, 0.f, 0.f);
#pragma unroll
    for (int k = 0; k < TK_; k++) {
        float w  = ws[k];
        float4 v = V4[(size_t)is[k]*(D_/4) + d4];
        acc.x = fmaf(w, v.x, acc.x);
        acc.y = fmaf(w, v.y, acc.y);
        acc.z = fmaf(w, v.z, acc.z);
        acc.w = fmaf(w, v.w, acc.w);
    }
    out4[(size_t)t*(D_/4) + d4] = acc;
}

// ---------------- launch ----------------
extern "C" void kernel_launch(void* const* d_in, const int* in_sizes, int n_in,
                              void* d_out, int out_size) {
    const float* x  = (const float*)d_in[0];
    const float* mw = (const float*)d_in[1];
    const float* cn = (const float*)d_in[2];
    const float* kK = (const float*)d_in[3];
    const float* kV = (const float*)d_in[4];
    float* out = (float*)d_out;

    cudaFuncSetAttribute(score_mma_kernel, cudaFuncAttributeMaxDynamicSharedMemorySize, SMEM_SC);

    sc_kernel<<<dim3(B_, D_), R_>>>(mw, cn);
    kbf_kernel<<<(NK_*R_/4)/256, 256>>>((const float4*)kK);
    q_kernel<<<dim3(S_/64, B_), 256>>>(x);
    score_mma_kernel<<<dim3(NTOK/128, NSPLIT4), 256, SMEM_SC>>>();
    rescore_kernel<<<NTOK/8, 256>>>(kK, out, out_size);
    gather_kernel<<<NTOK, 256>>>((const float4*)kV, (float4*)out);
}